// round 2
// baseline (speedup 1.0000x reference)
#include <cuda_runtime.h>
#include <float.h>

#define N_NODES 100000
#define N_EDGES 1200000
#define IN_F 128
#define HID 64
#define OUT_F 40

// ---------------- device scratch (no allocations allowed) ----------------
__device__ int   g_deg[N_NODES];          // in-degree incl. self-loop
__device__ float g_dinv[N_NODES];
__device__ int   g_rowptr[N_NODES + 1];   // CSR row pointers (real edges only)
__device__ int   g_cur[N_NODES];          // fill cursors
__device__ int   g_csr[N_EDGES];          // src node per CSR slot
__device__ int   g_edge[2 * N_EDGES];     // int32 [src | dst]
__device__ int   g_is64;
__device__ float g_hs[(size_t)N_NODES * HID];    // dinv-scaled transformed feats
__device__ float g_h1[(size_t)N_NODES * HID];    // layer-1 activations

// ---------------- edge dtype detect + convert ----------------
__global__ void k_detect(const long long* __restrict__ ei, int n) {
    if (threadIdx.x == 0 && blockIdx.x == 0) {
        int ok = 1;
        #pragma unroll
        for (int i = 0; i < 16; i++) {
            long long v = ei[i];
            if (v < 0 || v >= n) ok = 0;
        }
        g_is64 = ok;
    }
}

__global__ void k_convert(const void* __restrict__ ei, int e) {
    int i = blockIdx.x * blockDim.x + threadIdx.x;
    if (i < 2 * e) {
        int v = g_is64 ? (int)((const long long*)ei)[i]
                       : ((const int*)ei)[i];
        g_edge[i] = v;
    }
}

// ---------------- degree / norm / CSR ----------------
__global__ void k_deg_init(int n) {
    int i = blockIdx.x * blockDim.x + threadIdx.x;
    if (i < n) g_deg[i] = 1;  // self-loop
}

__global__ void k_deg_count(int e) {
    int i = blockIdx.x * blockDim.x + threadIdx.x;
    if (i < e) atomicAdd(&g_deg[g_edge[e + i]], 1);  // dst half
}

__global__ void k_dinv(int n) {
    int i = blockIdx.x * blockDim.x + threadIdx.x;
    if (i < n) g_dinv[i] = rsqrtf((float)g_deg[i]);
}

// single-block exclusive scan over (deg-1) -> rowptr, cur
__global__ void k_scan(int n) {
    __shared__ int warpsum[32];
    __shared__ int s_carry;
    const int tid = threadIdx.x, lane = tid & 31, wid = tid >> 5;
    if (tid == 0) s_carry = 0;
    __syncthreads();

    for (int base = 0; base < n; base += 1024) {
        int i = base + tid;
        int v = (i < n) ? (g_deg[i] - 1) : 0;
        int incl = v;
        #pragma unroll
        for (int off = 1; off < 32; off <<= 1) {
            int t = __shfl_up_sync(0xffffffffu, incl, off);
            if (lane >= off) incl += t;
        }
        if (lane == 31) warpsum[wid] = incl;
        __syncthreads();
        if (wid == 0) {
            int ws = warpsum[lane];
            int wincl = ws;
            #pragma unroll
            for (int off = 1; off < 32; off <<= 1) {
                int t = __shfl_up_sync(0xffffffffu, wincl, off);
                if (lane >= off) wincl += t;
            }
            warpsum[lane] = wincl - ws;  // exclusive warp offsets
        }
        __syncthreads();
        int excl = s_carry + warpsum[wid] + (incl - v);
        if (i < n) { g_rowptr[i] = excl; g_cur[i] = excl; }
        __syncthreads();
        if (tid == 1023) s_carry += warpsum[31] + incl;  // + block total
        __syncthreads();
    }
    if (tid == 0) g_rowptr[n] = s_carry;
}

__global__ void k_fill(int e) {
    int i = blockIdx.x * blockDim.x + threadIdx.x;
    if (i < e) {
        int s = g_edge[i];
        int d = g_edge[e + i];
        int pos = atomicAdd(&g_cur[d], 1);
        g_csr[pos] = s;
    }
}

// ------- dense GEMM: g_hs[n,64] = (A[n,K] @ W[K,64]) * dinv[row] -------
template <int K>
__global__ void k_gemm_hs(const float* __restrict__ A, const float* __restrict__ W, int n) {
    __shared__ __align__(16) float sW[64 * 64];
    __shared__ float sA[64 * 65];

    const int t = threadIdx.x;           // 256 threads
    const int row0 = blockIdx.x * 64;
    const int ty = t >> 4, tx = t & 15;  // 16x16 thread tile
    const int r0 = ty * 4, c0 = tx * 4;

    float acc[4][4] = {};

    for (int k0 = 0; k0 < K; k0 += 64) {
        __syncthreads();
        for (int i = t; i < 64 * 64 / 4; i += 256)
            ((float4*)sW)[i] = ((const float4*)(W + (size_t)k0 * 64))[i];
        for (int i = t; i < 64 * 16; i += 256) {
            int r = i >> 4;
            int kc = (i & 15) * 4;
            float4 v = make_float4(0.f, 0.f, 0.f, 0.f);
            if (row0 + r < n)
                v = *(const float4*)(A + (size_t)(row0 + r) * K + k0 + kc);
            float* d = &sA[r * 65 + kc];
            d[0] = v.x; d[1] = v.y; d[2] = v.z; d[3] = v.w;
        }
        __syncthreads();

        #pragma unroll 8
        for (int kk = 0; kk < 64; kk++) {
            float4 w4 = *(float4*)&sW[kk * 64 + c0];
            #pragma unroll
            for (int j = 0; j < 4; j++) {
                float a = sA[(r0 + j) * 65 + kk];
                acc[j][0] += a * w4.x;
                acc[j][1] += a * w4.y;
                acc[j][2] += a * w4.z;
                acc[j][3] += a * w4.w;
            }
        }
    }

    #pragma unroll
    for (int j = 0; j < 4; j++) {
        int r = row0 + r0 + j;
        if (r < n) {
            float dv = g_dinv[r];
            *(float4*)&g_hs[(size_t)r * 64 + c0] =
                make_float4(acc[j][0] * dv, acc[j][1] * dv,
                            acc[j][2] * dv, acc[j][3] * dv);
        }
    }
}

// ---- aggregation: out[v] = act(dinv[v]*(hs[v] + sum_{dst=v} hs[src]) + b)
// one warp per node; lane owns feats {lane, lane+32}
__global__ void k_agg(const float* __restrict__ b, float* __restrict__ out,
                      int n, int do_relu) {
    int gw = (blockIdx.x * blockDim.x + threadIdx.x) >> 5;
    int lane = threadIdx.x & 31;
    if (gw >= n) return;

    int beg = g_rowptr[gw], end = g_rowptr[gw + 1];
    const float* hv = g_hs + (size_t)gw * 64;
    float a0 = hv[lane];
    float a1 = hv[lane + 32];

    int j = beg;
    for (; j + 1 < end; j += 2) {
        int s0 = g_csr[j];
        int s1 = g_csr[j + 1];
        const float* p0 = g_hs + (size_t)s0 * 64;
        const float* p1 = g_hs + (size_t)s1 * 64;
        float v00 = p0[lane], v01 = p0[lane + 32];
        float v10 = p1[lane], v11 = p1[lane + 32];
        a0 += v00 + v10;
        a1 += v01 + v11;
    }
    if (j < end) {
        const float* p = g_hs + (size_t)g_csr[j] * 64;
        a0 += p[lane];
        a1 += p[lane + 32];
    }

    float dv = g_dinv[gw];
    float v0 = a0 * dv + b[lane];
    float v1 = a1 * dv + b[lane + 32];
    if (do_relu) { v0 = fmaxf(v0, 0.f); v1 = fmaxf(v1, 0.f); }
    out[(size_t)gw * 64 + lane]      = v0;
    out[(size_t)gw * 64 + lane + 32] = v1;
}

// ------------- head: logits = emb @ Wc + bc, softmax, argmax -------------
__global__ void k_head(const float* __restrict__ emb, const float* __restrict__ Wc,
                       const float* __restrict__ bc, float* __restrict__ logits,
                       float* __restrict__ soft, float* __restrict__ hard, int n) {
    __shared__ float sW[64 * OUT_F];
    __shared__ float sb[OUT_F];
    __shared__ float sE[8][64];

    int t = threadIdx.x;
    for (int i = t; i < 64 * OUT_F; i += 256) sW[i] = Wc[i];
    if (t < OUT_F) sb[t] = bc[t];

    int w = t >> 5, lane = t & 31;
    int node = blockIdx.x * 8 + w;
    if (node < n) {
        sE[w][lane]      = emb[(size_t)node * 64 + lane];
        sE[w][lane + 32] = emb[(size_t)node * 64 + lane + 32];
    }
    __syncthreads();
    if (node >= n) return;

    float acc0 = sb[lane];
    float acc1 = (lane < 8) ? sb[lane + 32] : 0.f;
    #pragma unroll 8
    for (int k = 0; k < 64; k++) {
        float e = sE[w][k];
        acc0 += e * sW[k * OUT_F + lane];
        if (lane < 8) acc1 += e * sW[k * OUT_F + lane + 32];
    }

    logits[(size_t)node * OUT_F + lane] = acc0;
    if (lane < 8) logits[(size_t)node * OUT_F + lane + 32] = acc1;

    float m = fmaxf(acc0, (lane < 8) ? acc1 : -FLT_MAX);
    #pragma unroll
    for (int o = 16; o > 0; o >>= 1) m = fmaxf(m, __shfl_xor_sync(0xffffffffu, m, o));
    float e0 = __expf(acc0 - m);
    float e1 = (lane < 8) ? __expf(acc1 - m) : 0.f;
    float s = e0 + e1;
    #pragma unroll
    for (int o = 16; o > 0; o >>= 1) s += __shfl_xor_sync(0xffffffffu, s, o);
    float inv = 1.f / s;
    soft[(size_t)node * OUT_F + lane] = e0 * inv;
    if (lane < 8) soft[(size_t)node * OUT_F + lane + 32] = e1 * inv;

    int cand = 0x7fffffff;
    if (acc0 == m) cand = lane;
    if (lane < 8 && acc1 == m) cand = min(cand, lane + 32);
    #pragma unroll
    for (int o = 16; o > 0; o >>= 1) cand = min(cand, __shfl_xor_sync(0xffffffffu, cand, o));
    if (lane == 0) hard[node] = (float)cand;
}

extern "C" void kernel_launch(void* const* d_in, const int* in_sizes, int n_in,
                              void* d_out, int out_size) {
    const float* x  = (const float*)d_in[0];
    const void*  ei = d_in[1];
    const float* W1 = (const float*)d_in[2];
    const float* b1 = (const float*)d_in[3];
    const float* W2 = (const float*)d_in[4];
    const float* b2 = (const float*)d_in[5];
    const float* Wc = (const float*)d_in[6];
    const float* bc = (const float*)d_in[7];

    const int N = in_sizes[0] / IN_F;
    const int E = in_sizes[1] / 2;

    float* outp   = (float*)d_out;
    float* logits = outp;
    float* emb    = outp + (size_t)N * OUT_F;
    float* soft   = emb  + (size_t)N * HID;
    float* hard   = soft + (size_t)N * OUT_F;

    const int TB = 256;

    // edge conversion + CSR build (int atomics only)
    k_detect<<<1, 32>>>((const long long*)ei, N);
    k_convert<<<(2 * E + TB - 1) / TB, TB>>>(ei, E);
    k_deg_init<<<(N + TB - 1) / TB, TB>>>(N);
    k_deg_count<<<(E + TB - 1) / TB, TB>>>(E);
    k_dinv<<<(N + TB - 1) / TB, TB>>>(N);
    k_scan<<<1, 1024>>>(N);
    k_fill<<<(E + TB - 1) / TB, TB>>>(E);

    // layer 1: g_hs = (x@W1)*dinv ; g_h1 = relu(agg + b1)
    k_gemm_hs<IN_F><<<(N + 63) / 64, 256>>>(x, W1, N);
    {
        float* h1ptr = nullptr;  // bound inside kernel via symbol
        (void)h1ptr;
    }
    k_agg<<<((N * 32) + TB - 1) / TB, TB>>>(b1, g_h1, N, 1);

    // layer 2: g_hs = (g_h1@W2)*dinv ; emb = agg + b2
    k_gemm_hs<HID><<<(N + 63) / 64, 256>>>(g_h1, W2, N);
    k_agg<<<((N * 32) + TB - 1) / TB, TB>>>(b2, emb, N, 0);

    // head
    k_head<<<(N + 7) / 8, 256>>>(emb, Wc, bc, logits, soft, hard, N);
}